// round 12
// baseline (speedup 1.0000x reference)
#include <cuda_runtime.h>
#include <cuda_bf16.h>
#include <math.h>
#include <stddef.h>
#include <stdint.h>

#define TT 512
#define BB 32
#define HH 256
#define NSTEP 64

// ---------------- scratch (static device arrays; no allocations) ----------------
__device__ float g_gx[(size_t)TT * BB * 2048];                     // x@Wih^T + b, both dirs
__device__ __align__(16) __nv_bfloat16 g_A2[(size_t)16384 * 3072]; // [Ahi | Ahi | Alo]
__device__ __align__(16) __nv_bfloat16 g_W2[(size_t)2048 * 3072];  // [Whi | Wlo | Whi]
__device__ float g_h[2][2 * BB * HH];
__device__ float g_c[2 * BB * HH];
__device__ float g_dh0[2][BB * HH];
__device__ float g_dh1[2][BB * HH];
__device__ unsigned g_cnt[4];
__device__ unsigned g_gen[4];
__device__ unsigned g_flag[128];          // per-slab (4 timesteps) GEMM completion counters

__device__ __forceinline__ float sigf(float x) { return 1.0f / (1.0f + expf(-x)); }

__device__ __forceinline__ uint32_t smem_u32(const void* p) {
    return (uint32_t)__cvta_generic_to_shared(p);
}
#define SMEM_SWIZZLE_128B(b) ((b) ^ (((b) >> 3) & 0x70))

// Software grid barrier among the 128 ENCODER blocks only (bids 0..127 are
// wave-1 co-resident by placement order; GEMM blocks never touch it).
__device__ __forceinline__ void gridbar(int id, unsigned nblk) {
    __threadfence();
    __syncthreads();
    if (threadIdx.x == 0) {
        volatile unsigned* genp = (volatile unsigned*)&g_gen[id];
        unsigned my = *genp;
        unsigned a = atomicAdd(&g_cnt[id], 1u);
        if (a == nblk - 1u) {
            atomicExch(&g_cnt[id], 0u);
            __threadfence();
            atomicAdd(&g_gen[id], 1u);
        } else {
            while (*genp == my) { }
        }
        __threadfence();
    }
    __syncthreads();
}

// ---------------- Phase 0: fp32 -> bf16 hi/lo split ----------------
__device__ __forceinline__ void split4(float4 v, uint2& hp, uint2& lp) {
    float f[4] = {v.x, v.y, v.z, v.w};
    unsigned short hu[4], lu[4];
#pragma unroll
    for (int j = 0; j < 4; j++) {
        __nv_bfloat16 h = __float2bfloat16(f[j]);
        float hf = __bfloat162float(h);
        __nv_bfloat16 l = __float2bfloat16(f[j] - hf);   // x - hi exact in fp32
        hu[j] = *(unsigned short*)&h;
        lu[j] = *(unsigned short*)&l;
    }
    hp.x = hu[0] | ((unsigned)hu[1] << 16); hp.y = hu[2] | ((unsigned)hu[3] << 16);
    lp.x = lu[0] | ((unsigned)lu[1] << 16); lp.y = lu[2] | ((unsigned)lu[3] << 16);
}

__global__ void __launch_bounds__(256) conv_a(const float* __restrict__ X) {
    size_t i = (size_t)blockIdx.x * 256 + threadIdx.x;
    float4 v = ((const float4*)X)[i];
    size_t e = i << 2;
    size_t m = e >> 10;
    int k = (int)(e & 1023);
    uint2 hp, lp;
    split4(v, hp, lp);
    __nv_bfloat16* rp = g_A2 + m * 3072 + k;
    *(uint2*)(rp)        = hp;
    *(uint2*)(rp + 1024) = hp;
    *(uint2*)(rp + 2048) = lp;
}

__global__ void __launch_bounds__(256) conv_w(const float* __restrict__ Wf, const float* __restrict__ Wb) {
    size_t i = (size_t)blockIdx.x * 256 + threadIdx.x;
    size_t e = i << 2;
    size_t n = e >> 10;
    int k = (int)(e & 1023);
    const float* src = (n < 1024) ? (Wf + n * 1024 + k) : (Wb + (n - 1024) * 1024 + k);
    float4 v = *(const float4*)src;
    uint2 hp, lp;
    split4(v, hp, lp);
    __nv_bfloat16* rp = g_W2 + n * 3072 + k;
    *(uint2*)(rp)        = hp;
    *(uint2*)(rp + 1024) = lp;
    *(uint2*)(rp + 2048) = hp;
}

// ---------------- Fused GEMM + encoder ----------------
// grid = 128 enc blocks + 2048 gemm blocks, 256 threads, 64 KB dynamic smem,
// 2 blocks/SM (reg cap 128). GEMM tile 128x128 (warp 64x32), K=3072, slabs of
// 128 M-rows (= 4 timesteps) produced from both sequence ends inward, completion
// published via g_flag[tb]. Encoder blocks poll the flag once per slab.
#define SM_A0 0
#define SM_A1 16384
#define SM_B0 32768
#define SM_B1 49152
#define FUSED_SMEM 65536
#define NC 48

__device__ __forceinline__ void cp16(uint32_t dst, const void* src) {
    asm volatile("cp.async.cg.shared.global [%0], [%1], 16;" :: "r"(dst), "l"(src));
}

__device__ void gemm_part(char* smem, const float* biasf, const float* biasb, int gid)
{
    const uint32_t sb = smem_u32(smem);
    const int tid = threadIdx.x;
    const int warp = tid >> 5, lane = tid & 31;
    const int by = gid & 15;
    const int s  = gid >> 4;
    const int tb = (s & 1) ? (127 - (s >> 1)) : (s >> 1);
    const int bm = tb * 128;
    const int bn = by * 128;
    const int warp_m = (warp & 1) * 64;
    const int warp_n = (warp >> 1) * 32;

    const __nv_bfloat16* Ab = g_A2 + (size_t)bm * 3072;
    const __nv_bfloat16* Bb = g_W2 + (size_t)bn * 3072;

    float acc[4][4][4];
#pragma unroll
    for (int im = 0; im < 4; im++)
#pragma unroll
        for (int in = 0; in < 4; in++)
#pragma unroll
            for (int q = 0; q < 4; q++) acc[im][in][q] = 0.0f;

    const int aj = tid & 7;

    auto load_stage = [&](int c, int buf) {
        const int kb = c * 64;
        const uint32_t dA = sb + (buf ? SM_A1 : SM_A0);
        const uint32_t dB = sb + (buf ? SM_B1 : SM_B0);
#pragma unroll
        for (int i = 0; i < 4; i++) {
            int row = (tid + i * 256) >> 3;
            cp16(dA + SMEM_SWIZZLE_128B(row * 128 + aj * 16),
                 Ab + (size_t)row * 3072 + kb + aj * 8);
        }
#pragma unroll
        for (int i = 0; i < 4; i++) {
            int row = (tid + i * 256) >> 3;
            cp16(dB + SMEM_SWIZZLE_128B(row * 128 + aj * 16),
                 Bb + (size_t)row * 3072 + kb + aj * 8);
        }
        asm volatile("cp.async.commit_group;" ::: "memory");
    };

    load_stage(0, 0);

    for (int c = 0; c < NC; c++) {
        const int cur = c & 1;
        if (c + 1 < NC) {
            load_stage(c + 1, cur ^ 1);
            asm volatile("cp.async.wait_group 1;" ::: "memory");
        } else {
            asm volatile("cp.async.wait_group 0;" ::: "memory");
        }
        __syncthreads();

        const uint32_t aBase = sb + (cur ? SM_A1 : SM_A0);
        const uint32_t bBase = sb + (cur ? SM_B1 : SM_B0);
#pragma unroll
        for (int ks = 0; ks < 4; ks++) {
            uint32_t af[4][4];
#pragma unroll
            for (int im = 0; im < 4; im++) {
                int row = warp_m + im * 16 + (lane & 15);
                uint32_t addr = aBase + SMEM_SWIZZLE_128B(row * 128 + ks * 32 + ((lane >> 4) << 4));
                asm volatile("ldmatrix.sync.aligned.m8n8.x4.shared.b16 {%0,%1,%2,%3}, [%4];"
                    : "=r"(af[im][0]), "=r"(af[im][1]), "=r"(af[im][2]), "=r"(af[im][3])
                    : "r"(addr));
            }
            uint32_t bfr[4][2];
#pragma unroll
            for (int ib = 0; ib < 2; ib++) {
                int row = warp_n + ib * 16 + (lane & 7) + (((lane >> 4) & 1) << 3);
                uint32_t addr = bBase + SMEM_SWIZZLE_128B(row * 128 + ks * 32 + (((lane >> 3) & 1) << 4));
                asm volatile("ldmatrix.sync.aligned.m8n8.x4.shared.b16 {%0,%1,%2,%3}, [%4];"
                    : "=r"(bfr[2 * ib][0]), "=r"(bfr[2 * ib][1]),
                      "=r"(bfr[2 * ib + 1][0]), "=r"(bfr[2 * ib + 1][1])
                    : "r"(addr));
            }
#pragma unroll
            for (int im = 0; im < 4; im++)
#pragma unroll
                for (int in = 0; in < 4; in++) {
                    asm volatile(
                        "mma.sync.aligned.m16n8k16.row.col.f32.bf16.bf16.f32 "
                        "{%0,%1,%2,%3}, {%4,%5,%6,%7}, {%8,%9}, {%0,%1,%2,%3};"
                        : "+f"(acc[im][in][0]), "+f"(acc[im][in][1]),
                          "+f"(acc[im][in][2]), "+f"(acc[im][in][3])
                        : "r"(af[im][0]), "r"(af[im][1]), "r"(af[im][2]), "r"(af[im][3]),
                          "r"(bfr[in][0]), "r"(bfr[in][1]));
                }
        }
        __syncthreads();
    }

    // epilogue: +bias, store fp32 rows; then publish slab completion
    const float* bp = (bn < 1024) ? (biasf + bn) : (biasb + (bn - 1024));
#pragma unroll
    for (int im = 0; im < 4; im++) {
        const int r0 = bm + warp_m + im * 16 + (lane >> 2);
#pragma unroll
        for (int in = 0; in < 4; in++) {
            const int cl = warp_n + in * 8 + (lane & 3) * 2;
            float bx = __ldg(bp + cl), by2 = __ldg(bp + cl + 1);
            float2 v0 = { acc[im][in][0] + bx, acc[im][in][1] + by2 };
            float2 v1 = { acc[im][in][2] + bx, acc[im][in][3] + by2 };
            *(float2*)(g_gx + (size_t)r0 * 2048 + bn + cl) = v0;
            *(float2*)(g_gx + (size_t)(r0 + 8) * 2048 + bn + cl) = v1;
        }
    }
    __threadfence();
    __syncthreads();
    if (tid == 0) atomicAdd(&g_flag[tb], 1u);
}

__device__ void enc_part(float* sm, const float* WhhF, const float* WhhB)
{
    float* sW = sm;                  // [16][260]
    float* sH = sW + 16 * 260;       // [32][260]
    float* sG = sH + 32 * 260;       // [16][33]
    float* sC = sG + 16 * 33;        // [128]
    const int dir = blockIdx.x >> 6;
    const int j0  = (blockIdx.x & 63) * 4;
    const int tid = threadIdx.x;
    const float* Whh = dir ? WhhB : WhhF;

    for (int i = tid; i < 16 * 256; i += 256) {
        int r = i >> 8, k = i & 255;
        int row = (r >> 2) * 256 + j0 + (r & 3);
        sW[r * 260 + k] = Whh[row * 256 + k];
    }
    for (int i = tid; i < 32 * 260; i += 256) sH[i] = 0.0f;
    if (tid < 128) sC[tid] = 0.0f;
    __syncthreads();

    const int b  = tid >> 3;
    const int qp = tid & 7;
    const int q0 = qp * 2, q1 = qp * 2 + 1;
    const int row0 = (q0 >> 2) * 256 + j0 + (q0 & 3);
    const int row1 = (q1 >> 2) * 256 + j0 + (q1 & 3);
    const float4* sH4 = (const float4*)sH;
    const float4* sW4 = (const float4*)sW;
    const int hbase4  = b * 65;
    const int w0base4 = q0 * 65, w1base4 = q1 * 65;
    float* hout0 = g_h[0] + dir * (BB * HH);
    float* hout1 = g_h[1] + dir * (BB * HH);

    int lastSlab = -1;
    for (int t = 0; t < TT; t++) {
        const int teff = dir ? (TT - 1 - t) : t;
        const int slab = teff >> 2;
        if (slab != lastSlab) {                 // wait for GEMM to finish this slab
            lastSlab = slab;
            if (tid == 0) {
                volatile unsigned* fp = (volatile unsigned*)&g_flag[slab];
                while (*fp < 16u) { }
            }
            __syncthreads();
        }
        const float* gxp = g_gx + (size_t)teff * (BB * 2048) + (size_t)b * 2048 + dir * 1024;
        float gx0 = gxp[row0];
        float gx1 = gxp[row1];
        float a0 = 0.0f, a1 = 0.0f;
#pragma unroll 8
        for (int k4 = 0; k4 < 64; k4++) {
            float4 hv = sH4[hbase4 + k4];
            float4 w0 = sW4[w0base4 + k4];
            float4 w1 = sW4[w1base4 + k4];
            a0 += w0.x * hv.x + w0.y * hv.y + w0.z * hv.z + w0.w * hv.w;
            a1 += w1.x * hv.x + w1.y * hv.y + w1.z * hv.z + w1.w * hv.w;
        }
        sG[q0 * 33 + b] = a0 + gx0;
        sG[q1 * 33 + b] = a1 + gx1;
        __syncthreads();
        float* hout = (t & 1) ? hout1 : hout0;
        if (tid < 128) {
            const int j = tid >> 5, bb = tid & 31;
            float gi = sG[(0 * 4 + j) * 33 + bb];
            float gf = sG[(1 * 4 + j) * 33 + bb];
            float gg = sG[(2 * 4 + j) * 33 + bb];
            float go = sG[(3 * 4 + j) * 33 + bb];
            float c  = sigf(gf) * sC[tid] + sigf(gi) * tanhf(gg);
            sC[tid] = c;
            hout[bb * 256 + j0 + j] = sigf(go) * tanhf(c);
        }
        gridbar(dir, 64);
        const float4* src = (const float4*)hout;
        float4* dst4 = (float4*)sH;
        for (int i = tid; i < 32 * 64; i += 256) {
            int bb = i >> 6, kk = i & 63;
            dst4[bb * 65 + kk] = __ldcg(src + bb * 64 + kk);
        }
        __syncthreads();
    }
    if (tid < 128) {
        const int j = tid >> 5, bb = tid & 31;
        g_c[dir * (BB * HH) + bb * 256 + j0 + j] = sC[tid];
    }
}

__global__ void __launch_bounds__(256, 2) fused_main(
    const float* __restrict__ WhhF, const float* __restrict__ WhhB,
    const float* __restrict__ biasf, const float* __restrict__ biasb)
{
    extern __shared__ char smem[];
    if (blockIdx.x < 128) {
        enc_part((float*)smem, WhhF, WhhB);
    } else {
        gemm_part(smem, biasf, biasb, blockIdx.x - 128);
    }
}

// ---------------- persistent decoder (unchanged, passing) ----------------
__global__ void __launch_bounds__(256) dec_persist(
    const float* __restrict__ Wih0, const float* __restrict__ Whh0, const float* __restrict__ b0v,
    const float* __restrict__ Wih1, const float* __restrict__ Whh1, const float* __restrict__ b1v,
    const float* __restrict__ linW, const float* __restrict__ linb,
    float* __restrict__ out)
{
    extern __shared__ float sm[];
    float* sWi0 = sm;
    float* sWh0 = sWi0 + 8 * 260;
    float* sWi1 = sWh0 + 8 * 260;
    float* sWh1 = sWi1 + 8 * 260;
    float* sX   = sWh1 + 8 * 260;
    float* sH   = sX + 32 * 260;
    float* sG   = sH + 32 * 260;
    float* sC   = sG + 8 * 33;
    const int tid = threadIdx.x;
    const int j0 = blockIdx.x * 2;

    for (int i = tid; i < 8 * 256; i += 256) {
        int r = i >> 8, k = i & 255;
        int row = (r >> 1) * 256 + j0 + (r & 1);
        sWi0[r * 260 + k] = Wih0[row * 256 + k];
        sWh0[r * 260 + k] = Whh0[row * 256 + k];
        sWi1[r * 260 + k] = Wih1[row * 256 + k];
        sWh1[r * 260 + k] = Whh1[row * 256 + k];
    }
    if (tid < 64) {
        int d = tid >> 5, bb = tid & 31;
        sC[tid]      = g_c[bb * 256 + j0 + d];
        sC[64 + tid] = g_c[BB * HH + bb * 256 + j0 + d];
    }
    __syncthreads();

    const float* hf = g_h[1];
    const float* hb = g_h[1] + BB * HH;
    const int b = tid >> 3, q = tid & 7;
    const int row = (q >> 1) * 256 + j0 + (q & 1);
    const float bias0 = b0v[row], bias1 = b1v[row];
    const float4* sX4 = (const float4*)sX;
    const float4* sH4 = (const float4*)sH;

    for (int t = 0; t < NSTEP; t++) {
        {
            float4* dX = (float4*)sX;
            float4* dH = (float4*)sH;
            const float4* srcX = (t == 0) ? (const float4*)0 : (const float4*)g_dh1[(t + 1) & 1];
            const float4* srcH = (t == 0) ? (const float4*)hf : (const float4*)g_dh0[(t + 1) & 1];
            for (int i = tid; i < 32 * 64; i += 256) {
                int bb = i >> 6, kk = i & 63;
                dX[bb * 65 + kk] = srcX ? __ldcg(srcX + bb * 64 + kk) : make_float4(0.f, 0.f, 0.f, 0.f);
                dH[bb * 65 + kk] = __ldcg(srcH + bb * 64 + kk);
            }
            __syncthreads();
            if (t > 0 && blockIdx.x == 0 && tid < 96) {
                int pb = tid / 3, pv = tid - pb * 3;
                float acc = linb[pv];
                const float* xr = sX + pb * 260;
                const float* wv = linW + pv * 256;
#pragma unroll 8
                for (int k = 0; k < 256; k++) acc += xr[k] * wv[k];
                out[(size_t)(t - 1) * 96 + pb * 3 + pv] = acc;
            }
            float a = 0.0f;
            const float4* wi4 = (const float4*)sWi0 + q * 65;
            const float4* wh4 = (const float4*)sWh0 + q * 65;
#pragma unroll 8
            for (int k4 = 0; k4 < 64; k4++) {
                float4 xv = sX4[b * 65 + k4], hv = sH4[b * 65 + k4];
                float4 wi = wi4[k4], wh = wh4[k4];
                a += wi.x * xv.x + wi.y * xv.y + wi.z * xv.z + wi.w * xv.w;
                a += wh.x * hv.x + wh.y * hv.y + wh.z * hv.z + wh.w * hv.w;
            }
            sG[q * 33 + b] = a + bias0;
            __syncthreads();
            if (tid < 64) {
                int d = tid >> 5, bb = tid & 31;
                float gi = sG[(0 * 2 + d) * 33 + bb];
                float gf = sG[(1 * 2 + d) * 33 + bb];
                float gg = sG[(2 * 2 + d) * 33 + bb];
                float go = sG[(3 * 2 + d) * 33 + bb];
                float c = sigf(gf) * sC[tid] + sigf(gi) * tanhf(gg);
                sC[tid] = c;
                g_dh0[t & 1][bb * 256 + j0 + d] = sigf(go) * tanhf(c);
            }
            gridbar(2, 128);
        }
        {
            float4* dX = (float4*)sX;
            float4* dH = (float4*)sH;
            const float4* srcX = (const float4*)g_dh0[t & 1];
            const float4* srcH = (t == 0) ? (const float4*)hb : (const float4*)g_dh1[(t + 1) & 1];
            for (int i = tid; i < 32 * 64; i += 256) {
                int bb = i >> 6, kk = i & 63;
                dX[bb * 65 + kk] = __ldcg(srcX + bb * 64 + kk);
                dH[bb * 65 + kk] = __ldcg(srcH + bb * 64 + kk);
            }
            __syncthreads();
            float a = 0.0f;
            const float4* wi4 = (const float4*)sWi1 + q * 65;
            const float4* wh4 = (const float4*)sWh1 + q * 65;
#pragma unroll 8
            for (int k4 = 0; k4 < 64; k4++) {
                float4 xv = sX4[b * 65 + k4], hv = sH4[b * 65 + k4];
                float4 wi = wi4[k4], wh = wh4[k4];
                a += wi.x * xv.x + wi.y * xv.y + wi.z * xv.z + wi.w * xv.w;
                a += wh.x * hv.x + wh.y * hv.y + wh.z * hv.z + wh.w * hv.w;
            }
            sG[q * 33 + b] = a + bias1;
            __syncthreads();
            if (tid < 64) {
                int d = tid >> 5, bb = tid & 31;
                float gi = sG[(0 * 2 + d) * 33 + bb];
                float gf = sG[(1 * 2 + d) * 33 + bb];
                float gg = sG[(2 * 2 + d) * 33 + bb];
                float go = sG[(3 * 2 + d) * 33 + bb];
                float c = sigf(gf) * sC[64 + tid] + sigf(gi) * tanhf(gg);
                sC[64 + tid] = c;
                g_dh1[t & 1][bb * 256 + j0 + d] = sigf(go) * tanhf(c);
            }
            gridbar(2, 128);
        }
    }
    if (blockIdx.x == 0 && tid < 96) {
        int pb = tid / 3, pv = tid - pb * 3;
        float acc = linb[pv];
        const float* xr = g_dh1[(NSTEP - 1) & 1] + pb * 256;
        const float* wv = linW + pv * 256;
#pragma unroll 8
        for (int k = 0; k < 256; k++) acc += __ldcg(xr + k) * wv[k];
        out[(size_t)(NSTEP - 1) * 96 + pb * 3 + pv] = acc;
    }
}

// ---------------- launch ----------------
extern "C" void kernel_launch(void* const* d_in, const int* in_sizes, int n_in,
                              void* d_out, int out_size)
{
    (void)in_sizes; (void)n_in; (void)out_size;
    const float* cnn   = (const float*)d_in[0];
    const float* eWihF = (const float*)d_in[1];
    const float* eWhhF = (const float*)d_in[2];
    const float* ebF   = (const float*)d_in[3];
    const float* eWihB = (const float*)d_in[4];
    const float* eWhhB = (const float*)d_in[5];
    const float* ebB   = (const float*)d_in[6];
    const float* dWih0 = (const float*)d_in[7];
    const float* dWhh0 = (const float*)d_in[8];
    const float* db0   = (const float*)d_in[9];
    const float* dWih1 = (const float*)d_in[10];
    const float* dWhh1 = (const float*)d_in[11];
    const float* db1   = (const float*)d_in[12];
    const float* linW  = (const float*)d_in[13];
    const float* linb  = (const float*)d_in[14];
    float* out = (float*)d_out;

    const int dec_smem = (4 * 8 * 260 + 2 * 32 * 260 + 8 * 33 + 128) * 4;
    cudaFuncSetAttribute(fused_main,  cudaFuncAttributeMaxDynamicSharedMemorySize, FUSED_SMEM);
    cudaFuncSetAttribute(dec_persist, cudaFuncAttributeMaxDynamicSharedMemorySize, dec_smem);

    // Phase 0: bf16 hi/lo splits of activations and both Wih matrices
    conv_a<<<16384, 256>>>(cnn);
    conv_w<<<2048, 256>>>(eWihF, eWihB);

    // reset per-slab GEMM completion flags for this replay
    void* flagp = nullptr;
    cudaGetSymbolAddress(&flagp, g_flag);
    cudaMemsetAsync(flagp, 0, 128 * sizeof(unsigned));

    // Fused: input-projection GEMM (2048 blocks, both-ends-inward slab order)
    // overlapped with the entire encoder recurrence (128 persistent blocks)
    fused_main<<<128 + 2048, 256, FUSED_SMEM>>>(eWhhF, eWhhB, ebF, ebB);

    // Decoder + projections in one persistent launch
    dec_persist<<<128, 256, dec_smem>>>(dWih0, dWhh0, db0, dWih1, dWhh1, db1,
                                        linW, linb, out);
}

// round 16
// speedup vs baseline: 1.3881x; 1.3881x over previous
#include <cuda_runtime.h>
#include <cuda_bf16.h>
#include <math.h>
#include <stddef.h>
#include <stdint.h>

#define TT 512
#define BB 32
#define HH 256
#define NSTEP 64

// ---------------- scratch (static device arrays; no allocations) ----------------
__device__ float g_gx[(size_t)TT * BB * 2048];                     // x@Wih^T + b, both dirs
__device__ __align__(16) __nv_bfloat16 g_A2[(size_t)16384 * 3072]; // [Ahi | Ahi | Alo]
__device__ __align__(16) __nv_bfloat16 g_W2[(size_t)2048 * 3072];  // [Whi | Wlo | Whi]
__device__ float g_h[2][2 * BB * HH];
__device__ float g_c[2 * BB * HH];
__device__ float g_dh0[2][BB * HH];
__device__ float g_dh1[2][BB * HH];
__device__ unsigned g_cnt[4];                 // monotonic barrier counters (memset per replay)

__device__ __forceinline__ float sigf(float x) { return 1.0f / (1.0f + expf(-x)); }

__device__ __forceinline__ uint32_t smem_u32(const void* p) {
    return (uint32_t)__cvta_generic_to_shared(p);
}
#define SMEM_SWIZZLE_128B(b) ((b) ^ (((b) >> 3) & 0x70))

// Monotonic-counter grid barrier among co-resident blocks.
// Release = leading __threadfence + one L2 RMW; consumers poll cnt (no reset, no
// generation word, no trailing fence — subsequent h reads are __ldcg from L2).
__device__ __forceinline__ void gridbar_inc(int id, unsigned target) {
    __threadfence();
    __syncthreads();
    if (threadIdx.x == 0) {
        atomicAdd(&g_cnt[id], 1u);
        volatile unsigned* cp = (volatile unsigned*)&g_cnt[id];
        while (*cp < target) { }
    }
    __syncthreads();
}

// ---------------- Phase 0: fp32 -> bf16 hi/lo split ----------------
__device__ __forceinline__ void split4(float4 v, uint2& hp, uint2& lp) {
    float f[4] = {v.x, v.y, v.z, v.w};
    unsigned short hu[4], lu[4];
#pragma unroll
    for (int j = 0; j < 4; j++) {
        __nv_bfloat16 h = __float2bfloat16(f[j]);
        float hf = __bfloat162float(h);
        __nv_bfloat16 l = __float2bfloat16(f[j] - hf);   // x - hi exact in fp32
        hu[j] = *(unsigned short*)&h;
        lu[j] = *(unsigned short*)&l;
    }
    hp.x = hu[0] | ((unsigned)hu[1] << 16); hp.y = hu[2] | ((unsigned)hu[3] << 16);
    lp.x = lu[0] | ((unsigned)lu[1] << 16); lp.y = lu[2] | ((unsigned)lu[3] << 16);
}

__global__ void __launch_bounds__(256) conv_a(const float* __restrict__ X) {
    size_t i = (size_t)blockIdx.x * 256 + threadIdx.x;
    float4 v = ((const float4*)X)[i];
    size_t e = i << 2;
    size_t m = e >> 10;
    int k = (int)(e & 1023);
    uint2 hp, lp;
    split4(v, hp, lp);
    __nv_bfloat16* rp = g_A2 + m * 3072 + k;
    *(uint2*)(rp)        = hp;
    *(uint2*)(rp + 1024) = hp;
    *(uint2*)(rp + 2048) = lp;
}

__global__ void __launch_bounds__(256) conv_w(const float* __restrict__ Wf, const float* __restrict__ Wb) {
    size_t i = (size_t)blockIdx.x * 256 + threadIdx.x;
    size_t e = i << 2;
    size_t n = e >> 10;
    int k = (int)(e & 1023);
    const float* src = (n < 1024) ? (Wf + n * 1024 + k) : (Wb + (n - 1024) * 1024 + k);
    float4 v = *(const float4*)src;
    uint2 hp, lp;
    split4(v, hp, lp);
    __nv_bfloat16* rp = g_W2 + n * 3072 + k;
    *(uint2*)(rp)        = hp;
    *(uint2*)(rp + 1024) = lp;
    *(uint2*)(rp + 2048) = hp;
}

// ---------------- Phase 1: HMMA bf16 GEMM (128x128 tile, 2 CTAs/SM) ----------------
// C[16384, 2048], K=3072. grid = 2048 blocks (by fast -> A slab reuse in-wave; B
// fits L2 entirely). Warp tile 64x32, cp.async double buffer, 64 KB smem.
#define SM_A0 0
#define SM_A1 16384
#define SM_B0 32768
#define SM_B1 49152
#define GEMM_SMEM 65536
#define NC 48

__device__ __forceinline__ void cp16(uint32_t dst, const void* src) {
    asm volatile("cp.async.cg.shared.global [%0], [%1], 16;" :: "r"(dst), "l"(src));
}

__global__ void __launch_bounds__(256, 2) gemm_mma(const float* __restrict__ biasf,
                                                   const float* __restrict__ biasb)
{
    extern __shared__ char smem[];
    const uint32_t sb = smem_u32(smem);
    const int tid = threadIdx.x;
    const int warp = tid >> 5, lane = tid & 31;
    const int by = blockIdx.x & 15;
    const int tb = blockIdx.x >> 4;
    const int bm = tb * 128;
    const int bn = by * 128;
    const int warp_m = (warp & 1) * 64;
    const int warp_n = (warp >> 1) * 32;

    const __nv_bfloat16* Ab = g_A2 + (size_t)bm * 3072;
    const __nv_bfloat16* Bb = g_W2 + (size_t)bn * 3072;

    float acc[4][4][4];
#pragma unroll
    for (int im = 0; im < 4; im++)
#pragma unroll
        for (int in = 0; in < 4; in++)
#pragma unroll
            for (int q = 0; q < 4; q++) acc[im][in][q] = 0.0f;

    const int aj = tid & 7;

    auto load_stage = [&](int c, int buf) {
        const int kb = c * 64;
        const uint32_t dA = sb + (buf ? SM_A1 : SM_A0);
        const uint32_t dB = sb + (buf ? SM_B1 : SM_B0);
#pragma unroll
        for (int i = 0; i < 4; i++) {
            int row = (tid + i * 256) >> 3;
            cp16(dA + SMEM_SWIZZLE_128B(row * 128 + aj * 16),
                 Ab + (size_t)row * 3072 + kb + aj * 8);
        }
#pragma unroll
        for (int i = 0; i < 4; i++) {
            int row = (tid + i * 256) >> 3;
            cp16(dB + SMEM_SWIZZLE_128B(row * 128 + aj * 16),
                 Bb + (size_t)row * 3072 + kb + aj * 8);
        }
        asm volatile("cp.async.commit_group;" ::: "memory");
    };

    load_stage(0, 0);

    for (int c = 0; c < NC; c++) {
        const int cur = c & 1;
        if (c + 1 < NC) {
            load_stage(c + 1, cur ^ 1);
            asm volatile("cp.async.wait_group 1;" ::: "memory");
        } else {
            asm volatile("cp.async.wait_group 0;" ::: "memory");
        }
        __syncthreads();

        const uint32_t aBase = sb + (cur ? SM_A1 : SM_A0);
        const uint32_t bBase = sb + (cur ? SM_B1 : SM_B0);
#pragma unroll
        for (int ks = 0; ks < 4; ks++) {
            uint32_t af[4][4];
#pragma unroll
            for (int im = 0; im < 4; im++) {
                int row = warp_m + im * 16 + (lane & 15);
                uint32_t addr = aBase + SMEM_SWIZZLE_128B(row * 128 + ks * 32 + ((lane >> 4) << 4));
                asm volatile("ldmatrix.sync.aligned.m8n8.x4.shared.b16 {%0,%1,%2,%3}, [%4];"
                    : "=r"(af[im][0]), "=r"(af[im][1]), "=r"(af[im][2]), "=r"(af[im][3])
                    : "r"(addr));
            }
            uint32_t bfr[4][2];
#pragma unroll
            for (int ib = 0; ib < 2; ib++) {
                int row = warp_n + ib * 16 + (lane & 7) + (((lane >> 4) & 1) << 3);
                uint32_t addr = bBase + SMEM_SWIZZLE_128B(row * 128 + ks * 32 + (((lane >> 3) & 1) << 4));
                asm volatile("ldmatrix.sync.aligned.m8n8.x4.shared.b16 {%0,%1,%2,%3}, [%4];"
                    : "=r"(bfr[2 * ib][0]), "=r"(bfr[2 * ib][1]),
                      "=r"(bfr[2 * ib + 1][0]), "=r"(bfr[2 * ib + 1][1])
                    : "r"(addr));
            }
#pragma unroll
            for (int im = 0; im < 4; im++)
#pragma unroll
                for (int in = 0; in < 4; in++) {
                    asm volatile(
                        "mma.sync.aligned.m16n8k16.row.col.f32.bf16.bf16.f32 "
                        "{%0,%1,%2,%3}, {%4,%5,%6,%7}, {%8,%9}, {%0,%1,%2,%3};"
                        : "+f"(acc[im][in][0]), "+f"(acc[im][in][1]),
                          "+f"(acc[im][in][2]), "+f"(acc[im][in][3])
                        : "r"(af[im][0]), "r"(af[im][1]), "r"(af[im][2]), "r"(af[im][3]),
                          "r"(bfr[in][0]), "r"(bfr[in][1]));
                }
        }
        __syncthreads();
    }

    const float* bp = (bn < 1024) ? (biasf + bn) : (biasb + (bn - 1024));
#pragma unroll
    for (int im = 0; im < 4; im++) {
        const int r0 = bm + warp_m + im * 16 + (lane >> 2);
#pragma unroll
        for (int in = 0; in < 4; in++) {
            const int cl = warp_n + in * 8 + (lane & 3) * 2;
            float bx = __ldg(bp + cl), by2 = __ldg(bp + cl + 1);
            float2 v0 = { acc[im][in][0] + bx, acc[im][in][1] + by2 };
            float2 v1 = { acc[im][in][2] + bx, acc[im][in][3] + by2 };
            *(float2*)(g_gx + (size_t)r0 * 2048 + bn + cl) = v0;
            *(float2*)(g_gx + (size_t)(r0 + 8) * 2048 + bn + cl) = v1;
        }
    }
}

// ---------------- Phase 2: persistent encoder (slim barrier) ----------------
__global__ void __launch_bounds__(256) enc_persist(
    const float* __restrict__ WhhF, const float* __restrict__ WhhB)
{
    extern __shared__ float sm[];
    float* sW = sm;                  // [16][260]
    float* sH = sW + 16 * 260;       // [32][260]
    float* sG = sH + 32 * 260;       // [16][33]
    float* sC = sG + 16 * 33;        // [128]
    const int dir = blockIdx.x >> 6;
    const int j0  = (blockIdx.x & 63) * 4;
    const int tid = threadIdx.x;
    const float* Whh = dir ? WhhB : WhhF;

    for (int i = tid; i < 16 * 256; i += 256) {
        int r = i >> 8, k = i & 255;
        int row = (r >> 2) * 256 + j0 + (r & 3);
        sW[r * 260 + k] = Whh[row * 256 + k];
    }
    for (int i = tid; i < 32 * 260; i += 256) sH[i] = 0.0f;
    if (tid < 128) sC[tid] = 0.0f;
    __syncthreads();

    const int b  = tid >> 3;
    const int qp = tid & 7;
    const int q0 = qp * 2, q1 = qp * 2 + 1;
    const int row0 = (q0 >> 2) * 256 + j0 + (q0 & 3);
    const int row1 = (q1 >> 2) * 256 + j0 + (q1 & 3);
    const float4* sH4 = (const float4*)sH;
    const float4* sW4 = (const float4*)sW;
    const int hbase4  = b * 65;
    const int w0base4 = q0 * 65, w1base4 = q1 * 65;
    float* hout0 = g_h[0] + dir * (BB * HH);
    float* hout1 = g_h[1] + dir * (BB * HH);

    for (int t = 0; t < TT; t++) {
        const int teff = dir ? (TT - 1 - t) : t;
        const float* gxp = g_gx + (size_t)teff * (BB * 2048) + (size_t)b * 2048 + dir * 1024;
        float gx0 = gxp[row0];                    // issued early, consumed after dot loop
        float gx1 = gxp[row1];
        float a0 = 0.0f, a1 = 0.0f;
#pragma unroll 8
        for (int k4 = 0; k4 < 64; k4++) {
            float4 hv = sH4[hbase4 + k4];
            float4 w0 = sW4[w0base4 + k4];
            float4 w1 = sW4[w1base4 + k4];
            a0 += w0.x * hv.x + w0.y * hv.y + w0.z * hv.z + w0.w * hv.w;
            a1 += w1.x * hv.x + w1.y * hv.y + w1.z * hv.z + w1.w * hv.w;
        }
        sG[q0 * 33 + b] = a0 + gx0;
        sG[q1 * 33 + b] = a1 + gx1;
        __syncthreads();
        float* hout = (t & 1) ? hout1 : hout0;
        if (tid < 128) {
            const int j = tid >> 5, bb = tid & 31;
            float gi = sG[(0 * 4 + j) * 33 + bb];
            float gf = sG[(1 * 4 + j) * 33 + bb];
            float gg = sG[(2 * 4 + j) * 33 + bb];
            float go = sG[(3 * 4 + j) * 33 + bb];
            float c  = sigf(gf) * sC[tid] + sigf(gi) * tanhf(gg);
            sC[tid] = c;
            hout[bb * 256 + j0 + j] = sigf(go) * tanhf(c);
        }
        gridbar_inc(dir, (unsigned)(t + 1) * 64u);
        const float4* src = (const float4*)hout;
        float4* dst4 = (float4*)sH;
        for (int i = tid; i < 32 * 64; i += 256) {
            int bb = i >> 6, kk = i & 63;
            dst4[bb * 65 + kk] = __ldcg(src + bb * 64 + kk);
        }
        __syncthreads();
    }
    if (tid < 128) {
        const int j = tid >> 5, bb = tid & 31;
        g_c[dir * (BB * HH) + bb * 256 + j0 + j] = sC[tid];
    }
}

// ---------------- Phase 3: persistent decoder (slim barrier) ----------------
__global__ void __launch_bounds__(256) dec_persist(
    const float* __restrict__ Wih0, const float* __restrict__ Whh0, const float* __restrict__ b0v,
    const float* __restrict__ Wih1, const float* __restrict__ Whh1, const float* __restrict__ b1v,
    const float* __restrict__ linW, const float* __restrict__ linb,
    float* __restrict__ out)
{
    extern __shared__ float sm[];
    float* sWi0 = sm;
    float* sWh0 = sWi0 + 8 * 260;
    float* sWi1 = sWh0 + 8 * 260;
    float* sWh1 = sWi1 + 8 * 260;
    float* sX   = sWh1 + 8 * 260;
    float* sH   = sX + 32 * 260;
    float* sG   = sH + 32 * 260;
    float* sC   = sG + 8 * 33;
    const int tid = threadIdx.x;
    const int j0 = blockIdx.x * 2;

    for (int i = tid; i < 8 * 256; i += 256) {
        int r = i >> 8, k = i & 255;
        int row = (r >> 1) * 256 + j0 + (r & 1);
        sWi0[r * 260 + k] = Wih0[row * 256 + k];
        sWh0[r * 260 + k] = Whh0[row * 256 + k];
        sWi1[r * 260 + k] = Wih1[row * 256 + k];
        sWh1[r * 260 + k] = Whh1[row * 256 + k];
    }
    if (tid < 64) {
        int d = tid >> 5, bb = tid & 31;
        sC[tid]      = g_c[bb * 256 + j0 + d];
        sC[64 + tid] = g_c[BB * HH + bb * 256 + j0 + d];
    }
    __syncthreads();

    const float* hf = g_h[1];
    const float* hb = g_h[1] + BB * HH;
    const int b = tid >> 3, q = tid & 7;
    const int row = (q >> 1) * 256 + j0 + (q & 1);
    const float bias0 = b0v[row], bias1 = b1v[row];
    const float4* sX4 = (const float4*)sX;
    const float4* sH4 = (const float4*)sH;
    unsigned barcnt = 0;

    for (int t = 0; t < NSTEP; t++) {
        {
            float4* dX = (float4*)sX;
            float4* dH = (float4*)sH;
            const float4* srcX = (t == 0) ? (const float4*)0 : (const float4*)g_dh1[(t + 1) & 1];
            const float4* srcH = (t == 0) ? (const float4*)hf : (const float4*)g_dh0[(t + 1) & 1];
            for (int i = tid; i < 32 * 64; i += 256) {
                int bb = i >> 6, kk = i & 63;
                dX[bb * 65 + kk] = srcX ? __ldcg(srcX + bb * 64 + kk) : make_float4(0.f, 0.f, 0.f, 0.f);
                dH[bb * 65 + kk] = __ldcg(srcH + bb * 64 + kk);
            }
            __syncthreads();
            if (t > 0 && blockIdx.x == 0 && tid < 96) {
                int pb = tid / 3, pv = tid - pb * 3;
                float acc = linb[pv];
                const float* xr = sX + pb * 260;
                const float* wv = linW + pv * 256;
#pragma unroll 8
                for (int k = 0; k < 256; k++) acc += xr[k] * wv[k];
                out[(size_t)(t - 1) * 96 + pb * 3 + pv] = acc;
            }
            float a = 0.0f;
            const float4* wi4 = (const float4*)sWi0 + q * 65;
            const float4* wh4 = (const float4*)sWh0 + q * 65;
#pragma unroll 8
            for (int k4 = 0; k4 < 64; k4++) {
                float4 xv = sX4[b * 65 + k4], hv = sH4[b * 65 + k4];
                float4 wi = wi4[k4], wh = wh4[k4];
                a += wi.x * xv.x + wi.y * xv.y + wi.z * xv.z + wi.w * xv.w;
                a += wh.x * hv.x + wh.y * hv.y + wh.z * hv.z + wh.w * hv.w;
            }
            sG[q * 33 + b] = a + bias0;
            __syncthreads();
            if (tid < 64) {
                int d = tid >> 5, bb = tid & 31;
                float gi = sG[(0 * 2 + d) * 33 + bb];
                float gf = sG[(1 * 2 + d) * 33 + bb];
                float gg = sG[(2 * 2 + d) * 33 + bb];
                float go = sG[(3 * 2 + d) * 33 + bb];
                float c = sigf(gf) * sC[tid] + sigf(gi) * tanhf(gg);
                sC[tid] = c;
                g_dh0[t & 1][bb * 256 + j0 + d] = sigf(go) * tanhf(c);
            }
            barcnt++;
            gridbar_inc(2, barcnt * 128u);
        }
        {
            float4* dX = (float4*)sX;
            float4* dH = (float4*)sH;
            const float4* srcX = (const float4*)g_dh0[t & 1];
            const float4* srcH = (t == 0) ? (const float4*)hb : (const float4*)g_dh1[(t + 1) & 1];
            for (int i = tid; i < 32 * 64; i += 256) {
                int bb = i >> 6, kk = i & 63;
                dX[bb * 65 + kk] = __ldcg(srcX + bb * 64 + kk);
                dH[bb * 65 + kk] = __ldcg(srcH + bb * 64 + kk);
            }
            __syncthreads();
            float a = 0.0f;
            const float4* wi4 = (const float4*)sWi1 + q * 65;
            const float4* wh4 = (const float4*)sWh1 + q * 65;
#pragma unroll 8
            for (int k4 = 0; k4 < 64; k4++) {
                float4 xv = sX4[b * 65 + k4], hv = sH4[b * 65 + k4];
                float4 wi = wi4[k4], wh = wh4[k4];
                a += wi.x * xv.x + wi.y * xv.y + wi.z * xv.z + wi.w * xv.w;
                a += wh.x * hv.x + wh.y * hv.y + wh.z * hv.z + wh.w * hv.w;
            }
            sG[q * 33 + b] = a + bias1;
            __syncthreads();
            if (tid < 64) {
                int d = tid >> 5, bb = tid & 31;
                float gi = sG[(0 * 2 + d) * 33 + bb];
                float gf = sG[(1 * 2 + d) * 33 + bb];
                float gg = sG[(2 * 2 + d) * 33 + bb];
                float go = sG[(3 * 2 + d) * 33 + bb];
                float c = sigf(gf) * sC[64 + tid] + sigf(gi) * tanhf(gg);
                sC[64 + tid] = c;
                g_dh1[t & 1][bb * 256 + j0 + d] = sigf(go) * tanhf(c);
            }
            barcnt++;
            gridbar_inc(2, barcnt * 128u);
        }
    }
    if (blockIdx.x == 0 && tid < 96) {
        int pb = tid / 3, pv = tid - pb * 3;
        float acc = linb[pv];
        const float* xr = g_dh1[(NSTEP - 1) & 1] + pb * 256;
        const float* wv = linW + pv * 256;
#pragma unroll 8
        for (int k = 0; k < 256; k++) acc += __ldcg(xr + k) * wv[k];
        out[(size_t)(NSTEP - 1) * 96 + pb * 3 + pv] = acc;
    }
}

// ---------------- launch ----------------
extern "C" void kernel_launch(void* const* d_in, const int* in_sizes, int n_in,
                              void* d_out, int out_size)
{
    (void)in_sizes; (void)n_in; (void)out_size;
    const float* cnn   = (const float*)d_in[0];
    const float* eWihF = (const float*)d_in[1];
    const float* eWhhF = (const float*)d_in[2];
    const float* ebF   = (const float*)d_in[3];
    const float* eWihB = (const float*)d_in[4];
    const float* eWhhB = (const float*)d_in[5];
    const float* ebB   = (const float*)d_in[6];
    const float* dWih0 = (const float*)d_in[7];
    const float* dWhh0 = (const float*)d_in[8];
    const float* db0   = (const float*)d_in[9];
    const float* dWih1 = (const float*)d_in[10];
    const float* dWhh1 = (const float*)d_in[11];
    const float* db1   = (const float*)d_in[12];
    const float* linW  = (const float*)d_in[13];
    const float* linb  = (const float*)d_in[14];
    float* out = (float*)d_out;

    const int enc_smem = (16 * 260 + 32 * 260 + 16 * 33 + 128) * 4;
    const int dec_smem = (4 * 8 * 260 + 2 * 32 * 260 + 8 * 33 + 128) * 4;
    cudaFuncSetAttribute(gemm_mma,    cudaFuncAttributeMaxDynamicSharedMemorySize, GEMM_SMEM);
    cudaFuncSetAttribute(enc_persist, cudaFuncAttributeMaxDynamicSharedMemorySize, enc_smem);
    cudaFuncSetAttribute(dec_persist, cudaFuncAttributeMaxDynamicSharedMemorySize, dec_smem);

    // reset monotonic barrier counters for this replay
    void* cntp = nullptr;
    cudaGetSymbolAddress(&cntp, g_cnt);
    cudaMemsetAsync(cntp, 0, 4 * sizeof(unsigned));

    // Phase 0: bf16 hi/lo splits of activations and both Wih matrices
    conv_a<<<16384, 256>>>(cnn);
    conv_w<<<2048, 256>>>(eWihF, eWihB);

    // Phase 1: HMMA bf16 3-term input-projection GEMM (128x128 tiles, 2 CTAs/SM)
    gemm_mma<<<2048, 256, GEMM_SMEM>>>(ebF, ebB);

    // Phase 2: entire encoder recurrence in one persistent launch
    enc_persist<<<128, 256, enc_smem>>>(eWhhF, eWhhB);

    // Phase 3: entire decoder + projections in one persistent launch
    dec_persist<<<128, 256, dec_smem>>>(dWih0, dWhh0, db0, dWih1, dWhh1, db1,
                                        linW, linb, out);
}